// round 14
// baseline (speedup 1.0000x reference)
#include <cuda_runtime.h>
#include <cstdint>
#include <cstddef>

#define RR 8
#define NN 300000
#define DD 128
#define AA 64
#define TILE_M 128
#define THREADS 128
#define HCH 36                 // h chunk row stride (32+4): frag banks 4g+tg distinct
#define WCH 72                 // w1 row stride (64+8): frag banks 8((tg+nt)&3)+g distinct
#define H_SLOT (TILE_M * HCH)  // 4608 floats
#define W_SLOT (32 * WCH)      // 2304 floats
#define NCH 32                 // 8 relations x 4 k-chunks
#define LOG2E 1.4426950408889634f

__device__ __forceinline__ float fast_sigmoid(float x) {
    float t;
    asm("tanh.approx.f32 %0, %1;" : "=f"(t) : "f"(0.5f * x));
    return fmaf(t, 0.5f, 0.5f);
}
__device__ __forceinline__ float fast_exp(float x) {
    float e; asm("ex2.approx.f32 %0, %1;" : "=f"(e) : "f"(LOG2E * x));
    return e;
}

__device__ __forceinline__ void mma_tf32_16n8k8(float c[4],
                                                const unsigned a[4],
                                                unsigned b0, unsigned b1) {
    asm volatile(
        "mma.sync.aligned.m16n8k8.row.col.f32.tf32.tf32.f32 "
        "{%0,%1,%2,%3}, {%4,%5,%6,%7}, {%8,%9}, {%0,%1,%2,%3};"
        : "+f"(c[0]), "+f"(c[1]), "+f"(c[2]), "+f"(c[3])
        : "r"(a[0]), "r"(a[1]), "r"(a[2]), "r"(a[3]), "r"(b0), "r"(b1));
}

__device__ __forceinline__ void cp_async16_s(uint32_t dst, const float* src) {
    asm volatile("cp.async.cg.shared.global [%0], [%1], 16;"
                 :: "r"(dst), "l"(src));
}
#define CP_COMMIT() asm volatile("cp.async.commit_group;")
#define CP_WAIT(n)  asm volatile("cp.async.wait_group %0;" :: "n"(n))

__device__ __forceinline__ float4 ldcs4(const float4* p) {
    float4 v;
    asm volatile("ld.global.cs.v4.f32 {%0,%1,%2,%3}, [%4];"
                 : "=f"(v.x), "=f"(v.y), "=f"(v.z), "=f"(v.w) : "l"(p));
    return v;
}
__device__ __forceinline__ void stcs4(float4* p, float4 v) {
    asm volatile("st.global.cs.v4.f32 [%0], {%1,%2,%3,%4};"
                 :: "l"(p), "f"(v.x), "f"(v.y), "f"(v.z), "f"(v.w));
}

__device__ __forceinline__ uint32_t smem_u32(const void* p) {
    uint32_t a;
    asm("{ .reg .u64 t; cvta.to.shared.u64 t, %1; cvt.u32.u64 %0, t; }"
        : "=r"(a) : "l"(p));
    return a;
}

__global__ void __launch_bounds__(THREADS, 3)
fused_kernel(const float* __restrict__ h,
             const float* __restrict__ w1,
             const float* __restrict__ w2,
             float* __restrict__ out) {
    extern __shared__ float smem[];
    float* sh_h   = smem;                       // 2 * H_SLOT
    float* sh_w   = sh_h + 2 * H_SLOT;          // 2 * W_SLOT
    float* sh_w2  = sh_w + 2 * W_SLOT;          // 512
    float* sh_sc  = sh_w2 + RR * AA;            // 8 * 128
    float* sh_prt = sh_sc + RR * TILE_M;        // 2 planes x 128

    const int tid = threadIdx.x;
    const long node0 = (long)blockIdx.x * TILE_M;
    const bool boundary = (node0 + TILE_M > NN);   // true for 1 block only

    sh_w2[tid]       = w2[tid];
    sh_w2[tid + 128] = w2[tid + 128];
    sh_w2[tid + 256] = w2[tid + 256];
    sh_w2[tid + 384] = w2[tid + 384];

    // ---- per-thread staging constants ----
    // h piece i (8 pieces of 128 granules): row = hrow0 + i*16, col granule hc4
    const int hrow0 = tid >> 3, hc4 = tid & 7;
    const size_t hoff0 = (size_t)(node0 + hrow0) * DD + hc4 * 4;
    const uint32_t hB = smem_u32(sh_h);
    const uint32_t hdst0 = hB + (uint32_t)(hrow0 * HCH + hc4 * 4) * 4;
    // w piece i (4 pieces of 128 granules): row = wrow0 + i*8, col granule wc4
    const int wrow0 = tid >> 4, wc4 = tid & 15;
    const size_t woff0 = (size_t)wrow0 * AA + wc4 * 4;
    const uint32_t wB = smem_u32(sh_w);
    const uint32_t wdst0 = wB + (uint32_t)(wrow0 * WCH + wc4 * 4) * 4;

    const size_t NND = (size_t)NN * DD;

    // per-piece global h offset (clamped only in the boundary block)
    auto h_off = [&](int i) -> size_t {
        if (!boundary) return hoff0 + (size_t)i * (16 * DD);
        long node = node0 + hrow0 + i * 16;
        if (node >= NN) node = NN - 1;
        return (size_t)node * DD + hc4 * 4;
    };

    // prologue: stage chunk 0 fully
    {
        const float* hs = h;                       // r=0, kc=0
        const float* ws = w1;
        #pragma unroll
        for (int i = 0; i < 8; i++)
            cp_async16_s(hdst0 + i * (16 * HCH * 4), hs + h_off(i));
        #pragma unroll
        for (int i = 0; i < 4; i++)
            cp_async16_s(wdst0 + i * (8 * WCH * 4), ws + woff0 + i * (8 * AA));
        CP_COMMIT();
    }

    const int w = tid >> 5, lane = tid & 31;
    const int g = lane >> 2, tg = lane & 3;
    const int m0 = (w & 1) * 64;   // 2-way m split (64 rows/warp)
    const int nh = w >> 1;         // 2-way n split (32 cols/warp)

    float acc[4][4][4];            // mt x nt x quad

    for (int c = 0; c < NCH; c++) {
        const int kc = c & 3;

        CP_WAIT(0);        // group for chunk c (committed during iter c-1) landed
        __syncthreads();   // publish slot c&1; all prior reads/writes ordered

        // lag-1 score write: relation (c-1)/4 finished its epilogue in iter c-1
        if (c >= 1 && (c & 3) == 0)
            sh_sc[((c - 1) >> 2) * TILE_M + tid] = sh_prt[tid] + sh_prt[TILE_M + tid];

        if (kc == 0) {
            #pragma unroll
            for (int mt = 0; mt < 4; mt++)
                #pragma unroll
                for (int nt = 0; nt < 4; nt++)
                    #pragma unroll
                    for (int q = 0; q < 4; q++) acc[mt][nt][q] = 0.f;
        }

        const unsigned* hh = (const unsigned*)(sh_h + (c & 1) * H_SLOT);
        const unsigned* ww = (const unsigned*)(sh_w + (c & 1) * W_SLOT);

        // next-chunk staging bases
        const bool do_stage = (c + 1 < NCH);
        const float* hsn = nullptr; const float* wsn = nullptr;
        uint32_t hdn = 0, wdn = 0;
        if (do_stage) {
            int cn = c + 1;
            hsn = h + (size_t)(cn >> 2) * NND + (cn & 3) * 32;
            wsn = w1 + (size_t)(cn >> 2) * (DD * AA) + (cn & 3) * (32 * AA);
            hdn = hdst0 + (uint32_t)((cn & 1) * H_SLOT * 4);
            wdn = wdst0 + (uint32_t)((cn & 1) * W_SLOT * 4);
        }

        #pragma unroll
        for (int kt = 0; kt < 4; kt++) {
            // de-burst staging of chunk c+1: 4 pieces per kt for kt=0..2
            if (do_stage) {
                if (kt < 2) {
                    #pragma unroll
                    for (int j = 0; j < 4; j++)
                        cp_async16_s(hdn + (4 * kt + j) * (16 * HCH * 4),
                                     hsn + h_off(4 * kt + j));
                } else if (kt == 2) {
                    #pragma unroll
                    for (int j = 0; j < 4; j++)
                        cp_async16_s(wdn + j * (8 * WCH * 4),
                                     wsn + woff0 + j * (8 * AA));
                    CP_COMMIT();
                }
            }
            unsigned a[4][4];
            #pragma unroll
            for (int mt = 0; mt < 4; mt++) {
                int row = m0 + mt * 16 + g;
                int col = kt * 8 + tg;
                a[mt][0] = hh[row * HCH + col];
                a[mt][1] = hh[(row + 8) * HCH + col];
                a[mt][2] = hh[row * HCH + col + 4];
                a[mt][3] = hh[(row + 8) * HCH + col + 4];
            }
            #pragma unroll
            for (int nt = 0; nt < 4; nt++) {
                int nb = nh * 32 + nt * 8;
                unsigned b0 = ww[(kt * 8 + tg) * WCH + nb + g];
                unsigned b1 = ww[(kt * 8 + tg + 4) * WCH + nb + g];
                #pragma unroll
                for (int mt = 0; mt < 4; mt++)
                    mma_tf32_16n8k8(acc[mt][nt], a[mt], b0, b1);
            }
        }

        if (kc == 3) {
            const int r = c >> 2;
            float slo[4] = {0.f, 0.f, 0.f, 0.f}, shi[4] = {0.f, 0.f, 0.f, 0.f};
            #pragma unroll
            for (int mt = 0; mt < 4; mt++)
                #pragma unroll
                for (int nt = 0; nt < 4; nt++) {
                    int cb = nh * 32 + nt * 8 + 2 * tg;
                    float wa = sh_w2[r * AA + cb], wb2 = sh_w2[r * AA + cb + 1];
                    slo[mt] += fast_sigmoid(acc[mt][nt][0]) * wa + fast_sigmoid(acc[mt][nt][1]) * wb2;
                    shi[mt] += fast_sigmoid(acc[mt][nt][2]) * wa + fast_sigmoid(acc[mt][nt][3]) * wb2;
                }
            #pragma unroll
            for (int o = 1; o < 4; o <<= 1) {
                #pragma unroll
                for (int mt = 0; mt < 4; mt++) {
                    slo[mt] += __shfl_xor_sync(0xffffffffu, slo[mt], o);
                    shi[mt] += __shfl_xor_sync(0xffffffffu, shi[mt], o);
                }
            }
            if (tg == 0) {
                #pragma unroll
                for (int mt = 0; mt < 4; mt++) {
                    sh_prt[nh * TILE_M + m0 + mt * 16 + g]     = slo[mt];
                    sh_prt[nh * TILE_M + m0 + mt * 16 + g + 8] = shi[mt];
                }
            }
        }
    }
    __syncthreads();   // prt for r=7 complete; ring slots final

    // final score (r=7) + softmax over relations (tid = row, 128 threads)
    {
        float sv[RR];
        sv[7] = sh_prt[tid] + sh_prt[TILE_M + tid];
        float m = sv[7];
        #pragma unroll
        for (int r = 0; r < 7; r++) { sv[r] = sh_sc[r * TILE_M + tid]; m = fmaxf(m, sv[r]); }
        float sum = 0.f;
        #pragma unroll
        for (int r = 0; r < RR; r++) { sv[r] = fast_exp(sv[r] - m); sum += sv[r]; }
        float inv = 1.f / sum;
        #pragma unroll
        for (int r = 0; r < RR; r++) sh_sc[r * TILE_M + tid] = sv[r] * inv;
    }
    __syncthreads();

    // phase 3: weighted sum. r=7 cols 64..127 from the smem ring
    // (slot0 = chunk30 = k[64:96), slot1 = chunk31 = k[96:128)); rest via .cs.
    const float4* hp = (const float4*)h;
    float4* op = (float4*)out;
    #pragma unroll 4
    for (int i = 0; i < 32; i++) {
        int idx = tid + i * THREADS;
        int nrow = idx >> 5, c4 = idx & 31;
        long node = node0 + nrow;
        if (node >= NN) continue;

        float a[RR];
        #pragma unroll
        for (int r = 0; r < RR; r++) a[r] = sh_sc[r * TILE_M + nrow];

        float4 acc4;
        {
            float4 v;
            if (c4 < 16) {
                v = ldcs4(&hp[((size_t)7 * NN + node) * 32 + c4]);
            } else {
                const float* sp = sh_h + ((c4 >> 3) & 1) * H_SLOT
                                + nrow * HCH + (c4 & 7) * 4;
                v = *(const float4*)sp;
            }
            acc4.x = a[7] * v.x; acc4.y = a[7] * v.y;
            acc4.z = a[7] * v.z; acc4.w = a[7] * v.w;
        }
        #pragma unroll
        for (int r = 6; r >= 0; r--) {
            float4 v = ldcs4(&hp[((size_t)r * NN + node) * 32 + c4]);
            acc4.x += a[r] * v.x; acc4.y += a[r] * v.y;
            acc4.z += a[r] * v.z; acc4.w += a[r] * v.w;
        }
        stcs4(&op[(size_t)node * 32 + c4], acc4);
    }
}

extern "C" void kernel_launch(void* const* d_in, const int* in_sizes, int n_in,
                              void* d_out, int out_size) {
    const float* h  = (const float*)d_in[0];
    const float* w1 = (const float*)d_in[1];
    const float* w2 = (const float*)d_in[2];
    float* out = (float*)d_out;

    const int smem_bytes =
        (2 * H_SLOT + 2 * W_SLOT + RR * AA + RR * TILE_M + 2 * TILE_M) * 4;  // ~61 KB
    cudaFuncSetAttribute(fused_kernel,
                         cudaFuncAttributeMaxDynamicSharedMemorySize, smem_bytes);

    dim3 grid((NN + TILE_M - 1) / TILE_M);
    fused_kernel<<<grid, THREADS, smem_bytes>>>(h, w1, w2, out);
}